// round 4
// baseline (speedup 1.0000x reference)
#include <cuda_runtime.h>
#include <cstdint>

// DynamicRouting: grouped 1x1 conv (G=8, FI=FO=64) + 3-iter sigmoid routing.
// B=32, H*W=4096, C=512. Fully fused, fp32, f32x2-packed FFMA conv.

#define G   8
#define FO  64
#define FI  64
#define HW  4096
#define C   512
#define BSZ 32
#define TP  64            // pixels per block
#define NTHREADS 256

#define XPAD 68           // x tile row stride (floats): 16B aligned rows, bank-clean
#define WPAD 65           // weight tile row stride: (o*65+i)%32 = (o+i)%32 -> conflict-free
#define CPAD 65           // con tile pixel-dim stride
#define CONG (FO*CPAD)    // floats per group in con tile: 4160

__device__ __forceinline__ uint32_t s2u(const void* p) {
    return (uint32_t)__cvta_generic_to_shared(p);
}
__device__ __forceinline__ void cp16(uint32_t d, const void* s) {
    asm volatile("cp.async.cg.shared.global [%0], [%1], 16;\n" :: "r"(d), "l"(s));
}
__device__ __forceinline__ void cp4(uint32_t d, const void* s) {
    asm volatile("cp.async.ca.shared.global [%0], [%1], 4;\n" :: "r"(d), "l"(s));
}
__device__ __forceinline__ void cp_commit() {
    asm volatile("cp.async.commit_group;\n");
}
template <int N>
__device__ __forceinline__ void cp_wait() {
    asm volatile("cp.async.wait_group %0;\n" :: "n"(N));
}

__device__ __forceinline__ uint64_t pack2(float v) {
    uint64_t r; asm("mov.b64 %0, {%1, %1};" : "=l"(r) : "f"(v)); return r;
}
__device__ __forceinline__ void unpack2(uint64_t v, float& lo, float& hi) {
    asm("mov.b64 {%0, %1}, %2;" : "=f"(lo), "=f"(hi) : "l"(v));
}
// packed 2-wide fp32 FMA (sm_100+): d = a*b + c elementwise on f32x2
__device__ __forceinline__ uint64_t ffma2(uint64_t a, uint64_t b, uint64_t c) {
    uint64_t d; asm("fma.rn.f32x2 %0, %1, %2, %3;" : "=l"(d) : "l"(a), "l"(b), "l"(c));
    return d;
}

__global__ __launch_bounds__(NTHREADS, 1)
void dynrout_kernel(const float* __restrict__ x,
                    const float* __restrict__ w,
                    const float* __restrict__ bias,
                    float* __restrict__ out)
{
    extern __shared__ float sm[];
    float* con = sm;                        // G * CONG              = 33280 floats
    float* xb  = sm + G * CONG;             // 2 * FI * XPAD         =  8704 floats
    float* wb  = xb + 2 * FI * XPAD;        // 2 * FO * WPAD         =  8320 floats

    const int tid = threadIdx.x;
    const int b   = blockIdx.x >> 6;        // 64 blocks per batch image
    const int p0  = (blockIdx.x & 63) << 6; // pixel tile start within HW

    const float* xblk = x + (size_t)b * C * HW + p0;

    // ---------------- async tile loader ----------------
    auto issue = [&](int g, int buf) {
        // x tile: 64 channels x 64 pixels fp32 = 1024 16B-chunks (16 per channel).
        // chunk id f: channel c = f >> 4, segment s = f & 15 (s*4 floats into the row).
        const float* xg = xblk + (size_t)g * FI * HW;
        uint32_t xdst = s2u(xb + buf * FI * XPAD);
        #pragma unroll
        for (int k = 0; k < 4; k++) {
            int f = k * NTHREADS + tid;     // 0..1023
            int c = f >> 4, s = f & 15;
            cp16(xdst + (uint32_t)(c * XPAD + s * 4) * 4, xg + (size_t)c * HW + s * 4);
        }
        // weight tile: 4096 floats, 4B chunks into padded rows (16 per thread)
        const float* wg = w + (size_t)g * FO * FI;
        uint32_t wdst = s2u(wb + buf * FO * WPAD);
        #pragma unroll
        for (int k = 0; k < 16; k++) {
            int f = k * NTHREADS + tid;     // 0..4095
            int o = f >> 6, i = f & 63;
            cp4(wdst + (uint32_t)(o * WPAD + i) * 4, wg + f);
        }
        cp_commit();
    };

    issue(0, 0);

    const int to    = tid & 63;             // this thread's output channel
    const int pbase = (tid >> 6) << 4;      // 0,16,32,48: 16-pixel slice

    // ---------------- conv: con[g][o][p] ----------------
    for (int g = 0; g < G; g++) {
        __syncthreads();                    // prior compute done -> safe to refill buf
        if (g < G - 1) { issue(g + 1, (g + 1) & 1); cp_wait<1>(); }
        else           { cp_wait<0>(); }
        __syncthreads();

        const float* xg = xb + (g & 1) * FI * XPAD;
        const float* wg = wb + (g & 1) * FO * WPAD;

        uint64_t acc[8];
        #pragma unroll
        for (int k = 0; k < 8; k++) acc[k] = 0ull;

        #pragma unroll 16
        for (int i = 0; i < FI; i++) {
            uint64_t w2 = pack2(wg[to * WPAD + i]);
            const ulonglong2* xp = (const ulonglong2*)(xg + i * XPAD + pbase);
            ulonglong2 q0 = xp[0], q1 = xp[1], q2 = xp[2], q3 = xp[3];
            acc[0] = ffma2(q0.x, w2, acc[0]);
            acc[1] = ffma2(q0.y, w2, acc[1]);
            acc[2] = ffma2(q1.x, w2, acc[2]);
            acc[3] = ffma2(q1.y, w2, acc[3]);
            acc[4] = ffma2(q2.x, w2, acc[4]);
            acc[5] = ffma2(q2.y, w2, acc[5]);
            acc[6] = ffma2(q3.x, w2, acc[6]);
            acc[7] = ffma2(q3.y, w2, acc[7]);
        }

        float* cg = con + g * CONG + to * CPAD + pbase;
        #pragma unroll
        for (int k = 0; k < 8; k++) {
            float lo, hi; unpack2(acc[k], lo, hi);
            cg[2 * k] = lo; cg[2 * k + 1] = hi;
        }
    }
    __syncthreads();

    // ---------------- routing epilogue: lanes = pixels ----------------
    if (tid < TP) {
        const int p = tid;
        const float* conp = con + p;        // + g*CONG + o*CPAD

        float beta[G];
        #pragma unroll
        for (int g = 0; g < G; g++) beta[g] = 0.f;

        #pragma unroll
        for (int it = 0; it < 2; it++) {
            float al[G], d[G];
            #pragma unroll
            for (int g = 0; g < G; g++) {
                al[g] = 1.f / (1.f + __expf(-beta[g]));
                d[g] = 0.f;
            }
            #pragma unroll 4
            for (int o = 0; o < FO; o++) {
                float c[G], vo = 0.f;
                #pragma unroll
                for (int g = 0; g < G; g++) c[g] = conp[g * CONG + o * CPAD];
                #pragma unroll
                for (int g = 0; g < G; g++) vo = fmaf(al[g], c[g], vo);
                #pragma unroll
                for (int g = 0; g < G; g++) d[g] = fmaf(vo, c[g], d[g]);
            }
            #pragma unroll
            for (int g = 0; g < G; g++) beta[g] += d[g];
        }

        float al[G];
        #pragma unroll
        for (int g = 0; g < G; g++) al[g] = 1.f / (1.f + __expf(-beta[g]));

        float* ob = out + (size_t)b * FO * HW + p0 + p;
        #pragma unroll 4
        for (int o = 0; o < FO; o++) {
            float vo = 0.f;
            #pragma unroll
            for (int g = 0; g < G; g++) vo = fmaf(al[g], conp[g * CONG + o * CPAD], vo);
            ob[(size_t)o * HW] = vo + __ldg(bias + o);
        }
    }
}

extern "C" void kernel_launch(void* const* d_in, const int* in_sizes, int n_in,
                              void* d_out, int out_size)
{
    const float* x    = (const float*)d_in[0];
    const float* wgt  = (const float*)d_in[1];
    const float* bias = (const float*)d_in[2];
    float* out        = (float*)d_out;

    const int smem_bytes = (G * CONG + 2 * FI * XPAD + 2 * FO * WPAD) * 4; // 201,216 B
    static int attr_set = 0;
    if (!attr_set) {
        cudaFuncSetAttribute(dynrout_kernel,
                             cudaFuncAttributeMaxDynamicSharedMemorySize, smem_bytes);
        attr_set = 1;
    }

    dim3 grid(BSZ * (HW / TP));  // 32 * 64 = 2048 blocks
    dynrout_kernel<<<grid, NTHREADS, smem_bytes>>>(x, wgt, bias, out);
}

// round 5
// speedup vs baseline: 1.0017x; 1.0017x over previous
#include <cuda_runtime.h>
#include <cstdint>

// DynamicRouting: grouped 1x1 conv (G=8, FI=FO=64) + 3-iter sigmoid routing.
// B=32, H*W=4096, C=512. Fully fused, fp32, f32x2-packed FFMA conv.

#define G   8
#define FO  64
#define FI  64
#define HW  4096
#define C   512
#define BSZ 32
#define TP  64            // pixels per block
#define NTHREADS 256

#define XPAD 68           // x tile row stride (floats): 16B aligned rows, bank-clean
#define WPAD 65           // weight tile row stride: (o*65+i)%32 = (o+i)%32 -> conflict-free
#define CPAD 65           // con tile pixel-dim stride
#define CONG (FO*CPAD)    // floats per group in con tile: 4160

__device__ __forceinline__ uint32_t s2u(const void* p) {
    return (uint32_t)__cvta_generic_to_shared(p);
}
__device__ __forceinline__ void cp16(uint32_t d, const void* s) {
    asm volatile("cp.async.cg.shared.global [%0], [%1], 16;\n" :: "r"(d), "l"(s));
}
__device__ __forceinline__ void cp4(uint32_t d, const void* s) {
    asm volatile("cp.async.ca.shared.global [%0], [%1], 4;\n" :: "r"(d), "l"(s));
}
__device__ __forceinline__ void cp_commit() {
    asm volatile("cp.async.commit_group;\n");
}
template <int N>
__device__ __forceinline__ void cp_wait() {
    asm volatile("cp.async.wait_group %0;\n" :: "n"(N));
}

__device__ __forceinline__ uint64_t pack2(float v) {
    uint64_t r; asm("mov.b64 %0, {%1, %1};" : "=l"(r) : "f"(v)); return r;
}
__device__ __forceinline__ void unpack2(uint64_t v, float& lo, float& hi) {
    asm("mov.b64 {%0, %1}, %2;" : "=f"(lo), "=f"(hi) : "l"(v));
}
// packed 2-wide fp32 FMA (sm_100+): d = a*b + c elementwise on f32x2
__device__ __forceinline__ uint64_t ffma2(uint64_t a, uint64_t b, uint64_t c) {
    uint64_t d; asm("fma.rn.f32x2 %0, %1, %2, %3;" : "=l"(d) : "l"(a), "l"(b), "l"(c));
    return d;
}

__global__ __launch_bounds__(NTHREADS, 1)
void dynrout_kernel(const float* __restrict__ x,
                    const float* __restrict__ w,
                    const float* __restrict__ bias,
                    float* __restrict__ out)
{
    extern __shared__ float sm[];
    float* con = sm;                        // G * CONG              = 33280 floats
    float* xb  = sm + G * CONG;             // 2 * FI * XPAD         =  8704 floats
    float* wb  = xb + 2 * FI * XPAD;        // 2 * FO * WPAD         =  8320 floats

    const int tid = threadIdx.x;
    const int b   = blockIdx.x >> 6;        // 64 blocks per batch image
    const int p0  = (blockIdx.x & 63) << 6; // pixel tile start within HW

    const float* xblk = x + (size_t)b * C * HW + p0;

    // ---------------- async tile loader ----------------
    auto issue = [&](int g, int buf) {
        // x tile: 64 channels x 64 pixels fp32 = 1024 16B-chunks (16 per channel).
        // chunk id f: channel c = f >> 4, segment s = f & 15 (s*4 floats into the row).
        const float* xg = xblk + (size_t)g * FI * HW;
        uint32_t xdst = s2u(xb + buf * FI * XPAD);
        #pragma unroll
        for (int k = 0; k < 4; k++) {
            int f = k * NTHREADS + tid;     // 0..1023
            int c = f >> 4, s = f & 15;
            cp16(xdst + (uint32_t)(c * XPAD + s * 4) * 4, xg + (size_t)c * HW + s * 4);
        }
        // weight tile: 4096 floats, 4B chunks into padded rows (16 per thread)
        const float* wg = w + (size_t)g * FO * FI;
        uint32_t wdst = s2u(wb + buf * FO * WPAD);
        #pragma unroll
        for (int k = 0; k < 16; k++) {
            int f = k * NTHREADS + tid;     // 0..4095
            int o = f >> 6, i = f & 63;
            cp4(wdst + (uint32_t)(o * WPAD + i) * 4, wg + f);
        }
        cp_commit();
    };

    issue(0, 0);

    const int to    = tid & 63;             // this thread's output channel
    const int pbase = (tid >> 6) << 4;      // 0,16,32,48: 16-pixel slice

    // ---------------- conv: con[g][o][p] ----------------
    for (int g = 0; g < G; g++) {
        __syncthreads();                    // prior compute done -> safe to refill buf
        if (g < G - 1) { issue(g + 1, (g + 1) & 1); cp_wait<1>(); }
        else           { cp_wait<0>(); }
        __syncthreads();

        const float* xg = xb + (g & 1) * FI * XPAD;
        const float* wg = wb + (g & 1) * FO * WPAD;

        uint64_t acc[8];
        #pragma unroll
        for (int k = 0; k < 8; k++) acc[k] = 0ull;

        #pragma unroll 16
        for (int i = 0; i < FI; i++) {
            uint64_t w2 = pack2(wg[to * WPAD + i]);
            const ulonglong2* xp = (const ulonglong2*)(xg + i * XPAD + pbase);
            ulonglong2 q0 = xp[0], q1 = xp[1], q2 = xp[2], q3 = xp[3];
            acc[0] = ffma2(q0.x, w2, acc[0]);
            acc[1] = ffma2(q0.y, w2, acc[1]);
            acc[2] = ffma2(q1.x, w2, acc[2]);
            acc[3] = ffma2(q1.y, w2, acc[3]);
            acc[4] = ffma2(q2.x, w2, acc[4]);
            acc[5] = ffma2(q2.y, w2, acc[5]);
            acc[6] = ffma2(q3.x, w2, acc[6]);
            acc[7] = ffma2(q3.y, w2, acc[7]);
        }

        float* cg = con + g * CONG + to * CPAD + pbase;
        #pragma unroll
        for (int k = 0; k < 8; k++) {
            float lo, hi; unpack2(acc[k], lo, hi);
            cg[2 * k] = lo; cg[2 * k + 1] = hi;
        }
    }
    __syncthreads();

    // ---------------- routing epilogue: lanes = pixels ----------------
    if (tid < TP) {
        const int p = tid;
        const float* conp = con + p;        // + g*CONG + o*CPAD

        float beta[G];
        #pragma unroll
        for (int g = 0; g < G; g++) beta[g] = 0.f;

        #pragma unroll
        for (int it = 0; it < 2; it++) {
            float al[G], d[G];
            #pragma unroll
            for (int g = 0; g < G; g++) {
                al[g] = 1.f / (1.f + __expf(-beta[g]));
                d[g] = 0.f;
            }
            #pragma unroll 4
            for (int o = 0; o < FO; o++) {
                float c[G], vo = 0.f;
                #pragma unroll
                for (int g = 0; g < G; g++) c[g] = conp[g * CONG + o * CPAD];
                #pragma unroll
                for (int g = 0; g < G; g++) vo = fmaf(al[g], c[g], vo);
                #pragma unroll
                for (int g = 0; g < G; g++) d[g] = fmaf(vo, c[g], d[g]);
            }
            #pragma unroll
            for (int g = 0; g < G; g++) beta[g] += d[g];
        }

        float al[G];
        #pragma unroll
        for (int g = 0; g < G; g++) al[g] = 1.f / (1.f + __expf(-beta[g]));

        float* ob = out + (size_t)b * FO * HW + p0 + p;
        #pragma unroll 4
        for (int o = 0; o < FO; o++) {
            float vo = 0.f;
            #pragma unroll
            for (int g = 0; g < G; g++) vo = fmaf(al[g], conp[g * CONG + o * CPAD], vo);
            ob[(size_t)o * HW] = vo + __ldg(bias + o);
        }
    }
}

extern "C" void kernel_launch(void* const* d_in, const int* in_sizes, int n_in,
                              void* d_out, int out_size)
{
    const float* x    = (const float*)d_in[0];
    const float* wgt  = (const float*)d_in[1];
    const float* bias = (const float*)d_in[2];
    float* out        = (float*)d_out;

    const int smem_bytes = (G * CONG + 2 * FI * XPAD + 2 * FO * WPAD) * 4; // 201,216 B
    static int attr_set = 0;
    if (!attr_set) {
        cudaFuncSetAttribute(dynrout_kernel,
                             cudaFuncAttributeMaxDynamicSharedMemorySize, smem_bytes);
        attr_set = 1;
    }

    dim3 grid(BSZ * (HW / TP));  // 32 * 64 = 2048 blocks
    dynrout_kernel<<<grid, NTHREADS, smem_bytes>>>(x, wgt, bias, out);
}

// round 6
// speedup vs baseline: 1.2644x; 1.2622x over previous
#include <cuda_runtime.h>
#include <cstdint>

// DynamicRouting: grouped 1x1 conv (G=8, FI=FO=64) + 3-iter sigmoid routing.
// B=32, H*W=4096. Fused fp32; conv uses 4o x 4px register tiles + fma.rn.f32x2.

#define G   8
#define FO  64
#define FI  64
#define HW  4096
#define C   512
#define BSZ 32
#define TP  64            // pixels per block
#define NTHREADS 256

#define XPAD 68           // x tile row stride (floats), 16B-aligned rows
#define WTP  68           // transposed weight tile row stride (wt[i][o]), 16B-aligned
#define CPAD 65           // con pixel stride: epilogue reads conflict-free
#define CONG (FO*CPAD)    // 4160 floats per group

__device__ __forceinline__ uint32_t s2u(const void* p) {
    return (uint32_t)__cvta_generic_to_shared(p);
}
__device__ __forceinline__ void cp16(uint32_t d, const void* s) {
    asm volatile("cp.async.cg.shared.global [%0], [%1], 16;\n" :: "r"(d), "l"(s));
}
__device__ __forceinline__ void cp4(uint32_t d, const void* s) {
    asm volatile("cp.async.ca.shared.global [%0], [%1], 4;\n" :: "r"(d), "l"(s));
}
__device__ __forceinline__ void cp_commit() {
    asm volatile("cp.async.commit_group;\n");
}
template <int N>
__device__ __forceinline__ void cp_wait() {
    asm volatile("cp.async.wait_group %0;\n" :: "n"(N));
}

__device__ __forceinline__ uint64_t pack2(float v) {
    uint64_t r; asm("mov.b64 %0, {%1, %1};" : "=l"(r) : "f"(v)); return r;
}
__device__ __forceinline__ void unpack2(uint64_t v, float& lo, float& hi) {
    asm("mov.b64 {%0, %1}, %2;" : "=f"(lo), "=f"(hi) : "l"(v));
}
// packed 2-wide fp32 FMA (sm_100+)
__device__ __forceinline__ uint64_t ffma2(uint64_t a, uint64_t b, uint64_t c) {
    uint64_t d; asm("fma.rn.f32x2 %0, %1, %2, %3;" : "=l"(d) : "l"(a), "l"(b), "l"(c));
    return d;
}
__device__ __forceinline__ float sigmoidf(float b) {
    return 1.f / (1.f + __expf(-b));
}

__global__ __launch_bounds__(NTHREADS, 1)
void dynrout_kernel(const float* __restrict__ x,
                    const float* __restrict__ w,
                    const float* __restrict__ bias,
                    float* __restrict__ out)
{
    extern __shared__ float sm[];
    float* con = sm;                          // G*CONG           = 33280 floats
    float* xb  = con + G * CONG;              // 2*FI*XPAD        =  8704 floats
    float* wtb = xb + 2 * FI * XPAD;          // 2*FI*WTP         =  8704 floats
    float* pd  = wtb + 2 * FI * WTP;          // 4*8*64           =  2048 floats

    const int tid = threadIdx.x;
    const int b   = blockIdx.x >> 6;          // 64 pixel-tiles per image
    const int p0  = (blockIdx.x & 63) << 6;

    const float* xblk = x + (size_t)b * C * HW + p0;

    // ---------------- async tile loader ----------------
    auto issue = [&](int g, int buf) {
        // x tile: 64ch x 64px fp32 = 1024 16B-chunks; c = f>>4, s = f&15
        const float* xg = xblk + (size_t)g * FI * HW;
        uint32_t xdst = s2u(xb + buf * FI * XPAD);
        #pragma unroll
        for (int k = 0; k < 4; k++) {
            int f = k * NTHREADS + tid;       // 0..1023
            int c = f >> 4, s = f & 15;
            cp16(xdst + (uint32_t)(c * XPAD + s * 4) * 4, xg + (size_t)c * HW + s * 4);
        }
        // transposed weight tile wt[i][o]: gmem element f = o*64 + i (coalesced src)
        const float* wg = w + (size_t)g * FO * FI;
        uint32_t wdst = s2u(wtb + buf * FI * WTP);
        #pragma unroll
        for (int k = 0; k < 16; k++) {
            int f = k * NTHREADS + tid;       // 0..4095
            int o = f >> 6, i = f & 63;
            cp4(wdst + (uint32_t)(i * WTP + o) * 4, wg + f);
        }
        cp_commit();
    };

    issue(0, 0);

    // thread tile: 4 output channels x 4 pixels
    // warp contains 8 distinct o-tiles and 4 distinct p-tiles (broadcast-friendly)
    const int o_t = (tid & 7) | ((tid >> 7) << 3);   // 0..15
    const int p_t = (tid >> 3) & 15;                 // 0..15
    const int o_base = o_t << 2;
    const int p_base = p_t << 2;

    // ---------------- conv: con[g][o][p] ----------------
    for (int g = 0; g < G; g++) {
        __syncthreads();
        if (g < G - 1) { issue(g + 1, (g + 1) & 1); cp_wait<1>(); }
        else           { cp_wait<0>(); }
        __syncthreads();

        const float* xg = xb  + (g & 1) * FI * XPAD;
        const float* wg = wtb + (g & 1) * FI * WTP;

        uint64_t acc[8];                      // acc[2*j + k2]: o j (0..3), px pair k2
        #pragma unroll
        for (int k = 0; k < 8; k++) acc[k] = 0ull;

        #pragma unroll 16
        for (int i = 0; i < FI; i++) {
            ulonglong2 xq = *(const ulonglong2*)(xg + i * XPAD + p_base); // 4 px
            float4     wq = *(const float4*)   (wg + i * WTP  + o_base);  // 4 o
            uint64_t w0 = pack2(wq.x), w1 = pack2(wq.y);
            uint64_t w2 = pack2(wq.z), w3 = pack2(wq.w);
            acc[0] = ffma2(xq.x, w0, acc[0]);  acc[1] = ffma2(xq.y, w0, acc[1]);
            acc[2] = ffma2(xq.x, w1, acc[2]);  acc[3] = ffma2(xq.y, w1, acc[3]);
            acc[4] = ffma2(xq.x, w2, acc[4]);  acc[5] = ffma2(xq.y, w2, acc[5]);
            acc[6] = ffma2(xq.x, w3, acc[6]);  acc[7] = ffma2(xq.y, w3, acc[7]);
        }

        float* cg = con + g * CONG + o_base * CPAD + p_base;
        #pragma unroll
        for (int j = 0; j < 4; j++) {
            float a, bq, c2, d2;
            unpack2(acc[2 * j],     a,  bq);
            unpack2(acc[2 * j + 1], c2, d2);
            cg[j * CPAD + 0] = a;  cg[j * CPAD + 1] = bq;
            cg[j * CPAD + 2] = c2; cg[j * CPAD + 3] = d2;
        }
    }
    __syncthreads();

    // ---------------- routing epilogue: 256 threads = 64 px x 4 o-quarters ----
    {
        const int p  = tid & 63;
        const int oq = tid >> 6;
        const int o0 = oq << 4;               // 16 o's per thread
        const float* conp = con + p;          // + g*CONG + o*CPAD

        float beta[G];
        #pragma unroll
        for (int g = 0; g < G; g++) beta[g] = 0.f;

        #pragma unroll
        for (int it = 0; it < 2; it++) {
            float al[G], d[G];
            #pragma unroll
            for (int g = 0; g < G; g++) { al[g] = sigmoidf(beta[g]); d[g] = 0.f; }

            #pragma unroll 4
            for (int oo = 0; oo < 16; oo++) {
                const int o = o0 + oo;
                float c[G], vo = 0.f;
                #pragma unroll
                for (int g = 0; g < G; g++) c[g] = conp[g * CONG + o * CPAD];
                #pragma unroll
                for (int g = 0; g < G; g++) vo = fmaf(al[g], c[g], vo);
                #pragma unroll
                for (int g = 0; g < G; g++) d[g] = fmaf(vo, c[g], d[g]);
            }
            // reduce partial d over the 4 o-quarters via smem
            #pragma unroll
            for (int g = 0; g < G; g++) pd[(oq * G + g) * TP + p] = d[g];
            __syncthreads();
            #pragma unroll
            for (int g = 0; g < G; g++) {
                float s = 0.f;
                #pragma unroll
                for (int q = 0; q < 4; q++) s += pd[(q * G + g) * TP + p];
                beta[g] += s;
            }
            __syncthreads();                  // pd reused next iteration
        }

        float al[G];
        #pragma unroll
        for (int g = 0; g < G; g++) al[g] = sigmoidf(beta[g]);

        float* ob = out + (size_t)b * FO * HW + p0 + p;
        #pragma unroll 4
        for (int oo = 0; oo < 16; oo++) {
            const int o = o0 + oo;
            float vo = 0.f;
            #pragma unroll
            for (int g = 0; g < G; g++) vo = fmaf(al[g], conp[g * CONG + o * CPAD], vo);
            ob[(size_t)o * HW] = vo + __ldg(bias + o);
        }
    }
}

extern "C" void kernel_launch(void* const* d_in, const int* in_sizes, int n_in,
                              void* d_out, int out_size)
{
    const float* x    = (const float*)d_in[0];
    const float* wgt  = (const float*)d_in[1];
    const float* bias = (const float*)d_in[2];
    float* out        = (float*)d_out;

    const int smem_bytes = (G * CONG + 2 * FI * XPAD + 2 * FI * WTP + 4 * G * TP) * 4;
    static int attr_set = 0;
    if (!attr_set) {
        cudaFuncSetAttribute(dynrout_kernel,
                             cudaFuncAttributeMaxDynamicSharedMemorySize, smem_bytes);
        attr_set = 1;
    }

    dim3 grid(BSZ * (HW / TP));   // 2048
    dynrout_kernel<<<grid, NTHREADS, smem_bytes>>>(x, wgt, bias, out);
}